// round 9
// baseline (speedup 1.0000x reference)
#include <cuda_runtime.h>
#include <cstdint>
#include <math.h>

// Problem constants (fixed shapes)
#define T    2048
#define DM   1024
#define NE   8
#define FF   4096

#define KC   32            // K floats per pipeline chunk
#define PAD  36            // smem row stride in floats (32 + 4)
#define NSTAGE 3

// ---------------- scratch (static device globals; no allocation) ----------------
__device__ int   g_count[NE];
__device__ int   g_cursor[NE];
__device__ int   g_offset[NE];
__device__ int   g_topk_idx[T * 2];
__device__ float g_topk_w[T * 2];
__device__ int   g_tok[2 * T];
__device__ float g_wgt[2 * T];
__device__ float g_inter[(size_t)(2 * T) * FF];   // 64 MB fp32 scratch (tf32-rounded values)

#define DEVINL __device__ __forceinline__

DEVINL uint32_t smem_u32(const void* p) {
    uint32_t a;
    asm("{ .reg .u64 t; cvta.to.shared.u64 t, %1; cvt.u32.u64 %0, t; }" : "=r"(a) : "l"(p));
    return a;
}

DEVINL uint32_t to_tf32(float f) {
    uint32_t r;
    asm("cvt.rna.tf32.f32 %0, %1;" : "=r"(r) : "f"(f));
    return r;
}
DEVINL float tf32f(float f) { return __uint_as_float(to_tf32(f)); }

// convert a 4-reg ldmatrix fragment in place
DEVINL void cvt4(uint32_t* r) {
    r[0] = to_tf32(__uint_as_float(r[0]));
    r[1] = to_tf32(__uint_as_float(r[1]));
    r[2] = to_tf32(__uint_as_float(r[2]));
    r[3] = to_tf32(__uint_as_float(r[3]));
}

DEVINL void mma_tf32(float* d, const uint32_t* a, const uint32_t* b) {
    asm volatile(
        "mma.sync.aligned.m16n8k8.row.col.f32.tf32.tf32.f32 "
        "{%0,%1,%2,%3}, {%4,%5,%6,%7}, {%8,%9}, {%0,%1,%2,%3};"
        : "+f"(d[0]), "+f"(d[1]), "+f"(d[2]), "+f"(d[3])
        : "r"(a[0]), "r"(a[1]), "r"(a[2]), "r"(a[3]), "r"(b[0]), "r"(b[1]));
}

DEVINL void ldsm_x4(uint32_t addr, uint32_t* r) {
    asm volatile("ldmatrix.sync.aligned.m8n8.x4.shared.b16 {%0,%1,%2,%3}, [%4];"
        : "=r"(r[0]), "=r"(r[1]), "=r"(r[2]), "=r"(r[3]) : "r"(addr));
}

// cp.async 16B with zero-fill when invalid (src-size 0 reads nothing)
DEVINL void cp16(uint32_t dst, const void* src, bool valid) {
    asm volatile("cp.async.cg.shared.global [%0], [%1], 16, %2;"
        :: "r"(dst), "l"(src), "r"(valid ? 16u : 0u) : "memory");
}
DEVINL void cp16f(uint32_t dst, const void* src) {
    asm volatile("cp.async.cg.shared.global [%0], [%1], 16;"
        :: "r"(dst), "l"(src) : "memory");
}
#define CP_COMMIT() asm volatile("cp.async.commit_group;" ::: "memory")
#define CP_WAIT1()  asm volatile("cp.async.wait_group 1;" ::: "memory")

// ---------------- init ----------------
__global__ void init_kernel() {
    int i = threadIdx.x;
    if (i < NE) { g_count[i] = 0; g_cursor[i] = 0; }
}

// ---------------- router ----------------
__global__ void router_kernel(const float* __restrict__ x,
                              const float* __restrict__ gw,
                              float* __restrict__ logits_out) {
    int t = blockIdx.x;
    int warp = threadIdx.x >> 5;
    int lane = threadIdx.x & 31;
    const float* xr = x + (size_t)t * DM;
    const float* gr = gw + (size_t)warp * DM;
    float s = 0.f;
    for (int j = lane; j < DM; j += 32) s += xr[j] * gr[j];
    #pragma unroll
    for (int o = 16; o > 0; o >>= 1) s += __shfl_xor_sync(0xFFFFFFFFu, s, o);

    __shared__ float lg[NE];
    if (lane == 0) lg[warp] = s;
    __syncthreads();

    if (threadIdx.x == 0) {
        float mx = lg[0];
        #pragma unroll
        for (int e = 1; e < NE; e++) mx = fmaxf(mx, lg[e]);
        float p[NE];
        #pragma unroll
        for (int e = 0; e < NE; e++) p[e] = expf(lg[e] - mx);
        int i0 = 0;
        #pragma unroll
        for (int e = 1; e < NE; e++) if (p[e] > p[i0]) i0 = e;
        int i1 = -1;
        #pragma unroll
        for (int e = 0; e < NE; e++) {
            if (e == i0) continue;
            if (i1 < 0 || p[e] > p[i1]) i1 = e;
        }
        float inv = 1.f / (p[i0] + p[i1]);
        g_topk_idx[t * 2 + 0] = i0;
        g_topk_idx[t * 2 + 1] = i1;
        g_topk_w[t * 2 + 0] = p[i0] * inv;
        g_topk_w[t * 2 + 1] = p[i1] * inv;
        atomicAdd(&g_count[i0], 1);
        atomicAdd(&g_count[i1], 1);
        #pragma unroll
        for (int e = 0; e < NE; e++) logits_out[(size_t)t * NE + e] = lg[e];
    }
}

// ---------------- offsets + assignment (single block) ----------------
__global__ void assign_kernel() {
    if (threadIdx.x == 0) {
        int o = 0;
        #pragma unroll
        for (int e = 0; e < NE; e++) { g_offset[e] = o; o += g_count[e]; }
    }
    __syncthreads();
    for (int t = threadIdx.x; t < T; t += blockDim.x) {
        #pragma unroll
        for (int k = 0; k < 2; k++) {
            int e = g_topk_idx[t * 2 + k];
            int pos = atomicAdd(&g_cursor[e], 1);
            int g = g_offset[e] + pos;
            g_tok[g] = t;
            g_wgt[g] = g_topk_w[t * 2 + k];
        }
    }
}

// smem sizing (uint32 units)
#define TILE128_U32 (128 * PAD)                      // 4608
#define TILE256_U32 (256 * PAD)                      // 9216
#define G1_SMEM_U32 (128 + NSTAGE * 3 * TILE128_U32)                 // 41600 u32 = 166400 B
#define G2_SMEM_U32 (256 + NSTAGE * (TILE128_U32 + TILE256_U32))     // 41728 u32 = 166912 B
#define G1_SMEM_BYTES (G1_SMEM_U32 * 4)
#define G2_SMEM_BYTES (G2_SMEM_U32 * 4)

// ================= GEMM1: inter = silu(X w1^T) * (X w3^T) =================
// 256 threads, 8 warps (2M x 4N), block 128x128, warp tile 64x32 (mt=4, nt=4).
// cp.async 3-stage pipeline; cvt.rna applied to fragments after ldmatrix.
__global__ __launch_bounds__(256, 1)
void gemm1_tc(const float* __restrict__ x,
              const float* __restrict__ w1,
              const float* __restrict__ w3) {
    int e = blockIdx.z;
    int cnt = g_count[e];
    int m0 = blockIdx.y * 128;
    if (m0 >= cnt) return;
    int n0 = blockIdx.x * 128;
    int base = g_offset[e];

    extern __shared__ uint32_t sm[];
    int* toks = (int*)sm;
    uint32_t* Abuf  = sm + 128;                        // NSTAGE x TILE128
    uint32_t* B1buf = Abuf  + NSTAGE * TILE128_U32;
    uint32_t* B3buf = B1buf + NSTAGE * TILE128_U32;

    uint32_t sbA  = smem_u32(Abuf);
    uint32_t sbB1 = smem_u32(B1buf);
    uint32_t sbB3 = smem_u32(B3buf);

    int tid = threadIdx.x;
    int wid = tid >> 5, lane = tid & 31;
    int g = lane >> 2, tq = lane & 3;
    int grp = lane >> 3, rowi = lane & 7;
    int warpM = wid >> 2, warpN = wid & 3;     // 2(M) x 4(N)

    if (tid < 128) {
        int m = m0 + tid;
        toks[tid] = (m < cnt) ? g_tok[base + m] : -1;
    }
    __syncthreads();

    const float* W1 = w1 + (size_t)e * FF * DM + (size_t)n0 * DM;
    const float* W3 = w3 + (size_t)e * FF * DM + (size_t)n0 * DM;

    float acc1[4][4][4], acc3[4][4][4];
    #pragma unroll
    for (int i = 0; i < 4; i++)
        #pragma unroll
        for (int j = 0; j < 4; j++)
            #pragma unroll
            for (int c = 0; c < 4; c++) { acc1[i][j][c] = 0.f; acc3[i][j][c] = 0.f; }

    // producer: per chunk 128 rows x 8 float4 per tile; 256 thr -> 4 cp.async per tile
    int prow = tid >> 1;              // 0..127 (2 threads per row)
    int pj0  = (tid & 1) * 4;         // f4 index 0..3 / 4..7
    int ptok = toks[prow];
    const float* aSrc = (ptok >= 0) ? (x + (size_t)ptok * DM) : x;
    const float* b1Src = W1 + (size_t)prow * DM;
    const float* b3Src = W3 + (size_t)prow * DM;
    uint32_t dOff = (uint32_t)(prow * PAD) * 4;

    auto load_chunk = [&](int it) {
        int s = it - (it / NSTAGE) * NSTAGE;
        int k0 = it * KC;
        uint32_t A  = sbA  + (uint32_t)(s * TILE128_U32) * 4 + dOff;
        uint32_t B1 = sbB1 + (uint32_t)(s * TILE128_U32) * 4 + dOff;
        uint32_t B3 = sbB3 + (uint32_t)(s * TILE128_U32) * 4 + dOff;
        #pragma unroll
        for (int j = 0; j < 4; j++) {
            int jj = pj0 + j;
            cp16(A + (uint32_t)(jj * 16), aSrc + k0 + jj * 4, ptok >= 0);
            cp16f(B1 + (uint32_t)(jj * 16), b1Src + k0 + jj * 4);
            cp16f(B3 + (uint32_t)(jj * 16), b3Src + k0 + jj * 4);
        }
        CP_COMMIT();
    };

    auto compute_chunk = [&](int s) {
        uint32_t Ab  = sbA  + (uint32_t)(s * TILE128_U32) * 4;
        uint32_t B1b = sbB1 + (uint32_t)(s * TILE128_U32) * 4;
        uint32_t B3b = sbB3 + (uint32_t)(s * TILE128_U32) * 4;
        #pragma unroll
        for (int ks = 0; ks < 4; ks++) {
            uint32_t afr[4][4];
            #pragma unroll
            for (int mt = 0; mt < 4; mt++) {
                int arow = warpM * 64 + mt * 16 + (grp & 1) * 8 + rowi;
                uint32_t addr = Ab + (uint32_t)(arow * PAD + ks * 8 + (grp >> 1) * 4) * 4;
                ldsm_x4(addr, afr[mt]);
                cvt4(afr[mt]);
            }
            uint32_t b1f[2][4], b3f[2][4];
            #pragma unroll
            for (int np = 0; np < 2; np++) {
                int nrow = warpN * 32 + np * 16 + (grp >> 1) * 8 + rowi;
                uint32_t off = (uint32_t)(nrow * PAD + ks * 8 + (grp & 1) * 4) * 4;
                ldsm_x4(B1b + off, b1f[np]);
                ldsm_x4(B3b + off, b3f[np]);
                cvt4(b1f[np]);
                cvt4(b3f[np]);
            }
            #pragma unroll
            for (int np = 0; np < 2; np++) {
                #pragma unroll
                for (int sub = 0; sub < 2; sub++) {
                    int nt = np * 2 + sub;
                    #pragma unroll
                    for (int mt = 0; mt < 4; mt++) {
                        mma_tf32(acc1[mt][nt], afr[mt], &b1f[np][sub * 2]);
                        mma_tf32(acc3[mt][nt], afr[mt], &b3f[np][sub * 2]);
                    }
                }
            }
        }
    };

    const int NIT = DM / KC;   // 32
    load_chunk(0);
    load_chunk(1);
    int s = 0;
    for (int it = 0; it < NIT; ++it) {
        CP_WAIT1();
        __syncthreads();
        if (it + 2 < NIT) load_chunk(it + 2);
        compute_chunk(s);
        s++; if (s == NSTAGE) s = 0;
    }

    // epilogue: silu(up) * gate, tf32-rounded -> g_inter (valid rows only)
    #pragma unroll
    for (int mt = 0; mt < 4; mt++) {
        #pragma unroll
        for (int half = 0; half < 2; half++) {
            int rl = warpM * 64 + mt * 16 + half * 8 + g;
            int m = m0 + rl;
            if (m < cnt) {
                float* orow = g_inter + (size_t)(base + m) * FF + n0;
                #pragma unroll
                for (int nt = 0; nt < 4; nt++) {
                    int col = warpN * 32 + nt * 8 + 2 * tq;
                    float u0 = acc1[mt][nt][half * 2 + 0];
                    float u1 = acc1[mt][nt][half * 2 + 1];
                    float g0 = acc3[mt][nt][half * 2 + 0];
                    float g1 = acc3[mt][nt][half * 2 + 1];
                    float2 o;
                    o.x = tf32f(u0 / (1.f + __expf(-u0)) * g0);
                    o.y = tf32f(u1 / (1.f + __expf(-u1)) * g1);
                    *(float2*)(orow + col) = o;
                }
            }
        }
    }
}

// ================= GEMM2: out += cw * (inter w2^T) =================
// 256 threads, 8 warps (2M x 4N), block 128x256, warp tile 64x64 (mt=4, nt=8).
// A (g_inter) is pre-rounded tf32 -> no cvt; B (w2) cvt after ldmatrix.
__global__ __launch_bounds__(256, 1)
void gemm2_tc(const float* __restrict__ w2, float* __restrict__ out) {
    int e = blockIdx.z;
    int cnt = g_count[e];
    int m0 = blockIdx.y * 128;
    if (m0 >= cnt) return;
    int n0 = blockIdx.x * 256;
    int base = g_offset[e];

    extern __shared__ uint32_t sm[];
    int*   toks = (int*)sm;                 // [128]
    float* wgts = (float*)(sm + 128);       // [128]
    uint32_t* Abuf = sm + 256;                          // NSTAGE x TILE128
    uint32_t* Bbuf = Abuf + NSTAGE * TILE128_U32;       // NSTAGE x TILE256

    uint32_t sbA = smem_u32(Abuf);
    uint32_t sbB = smem_u32(Bbuf);

    int tid = threadIdx.x;
    int wid = tid >> 5, lane = tid & 31;
    int g = lane >> 2, tq = lane & 3;
    int grp = lane >> 3, rowi = lane & 7;
    int warpM = wid >> 2, warpN = wid & 3;   // 2(M) x 4(N)

    if (tid < 128) {
        int m = m0 + tid;
        bool v = (m < cnt);
        toks[tid] = v ? g_tok[base + m] : -1;
        wgts[tid] = v ? g_wgt[base + m] : 0.f;
    }
    __syncthreads();

    const float* W2 = w2 + (size_t)e * DM * FF + (size_t)n0 * FF;
    const float* Ain = g_inter + (size_t)(base + m0) * FF;
    int mlim = cnt - m0;

    float acc[4][8][4];
    #pragma unroll
    for (int i = 0; i < 4; i++)
        #pragma unroll
        for (int j = 0; j < 8; j++)
            #pragma unroll
            for (int c = 0; c < 4; c++) acc[i][j][c] = 0.f;

    // producer: A 128 rows x 8 f4 (2 thr/row -> 4 each); B 256 rows x 8 f4 (1 thr/row -> 8 each)
    int parow = tid >> 1;
    int paj0  = (tid & 1) * 4;
    bool paval = (parow < mlim);
    const float* paSrc = Ain + (size_t)(paval ? parow : 0) * FF;
    uint32_t paOff = (uint32_t)(parow * PAD) * 4;
    const float* pbSrc = W2 + (size_t)tid * FF;
    uint32_t pbOff = (uint32_t)(tid * PAD) * 4;

    auto load_chunk = [&](int it) {
        int s = it - (it / NSTAGE) * NSTAGE;
        int k0 = it * KC;
        uint32_t A = sbA + (uint32_t)(s * TILE128_U32) * 4 + paOff;
        uint32_t B = sbB + (uint32_t)(s * TILE256_U32) * 4 + pbOff;
        #pragma unroll
        for (int j = 0; j < 4; j++) {
            int jj = paj0 + j;
            cp16(A + (uint32_t)(jj * 16), paSrc + k0 + jj * 4, paval);
        }
        #pragma unroll
        for (int j = 0; j < 8; j++)
            cp16f(B + (uint32_t)(j * 16), pbSrc + k0 + j * 4);
        CP_COMMIT();
    };

    auto compute_chunk = [&](int s) {
        uint32_t Ab = sbA + (uint32_t)(s * TILE128_U32) * 4;
        uint32_t Bb = sbB + (uint32_t)(s * TILE256_U32) * 4;
        #pragma unroll
        for (int ks = 0; ks < 4; ks++) {
            uint32_t afr[4][4];
            #pragma unroll
            for (int mt = 0; mt < 4; mt++) {
                int arow = warpM * 64 + mt * 16 + (grp & 1) * 8 + rowi;
                uint32_t addr = Ab + (uint32_t)(arow * PAD + ks * 8 + (grp >> 1) * 4) * 4;
                ldsm_x4(addr, afr[mt]);   // already tf32-rounded values
            }
            uint32_t bf[4][4];
            #pragma unroll
            for (int np = 0; np < 4; np++) {
                int nrow = warpN * 64 + np * 16 + (grp >> 1) * 8 + rowi;
                uint32_t off = (uint32_t)(nrow * PAD + ks * 8 + (grp & 1) * 4) * 4;
                ldsm_x4(Bb + off, bf[np]);
                cvt4(bf[np]);
            }
            #pragma unroll
            for (int np = 0; np < 4; np++) {
                #pragma unroll
                for (int sub = 0; sub < 2; sub++) {
                    int nt = np * 2 + sub;
                    #pragma unroll
                    for (int mt = 0; mt < 4; mt++)
                        mma_tf32(acc[mt][nt], afr[mt], &bf[np][sub * 2]);
                }
            }
        }
    };

    const int NIT = FF / KC;   // 128
    load_chunk(0);
    load_chunk(1);
    int s = 0;
    for (int it = 0; it < NIT; ++it) {
        CP_WAIT1();
        __syncthreads();
        if (it + 2 < NIT) load_chunk(it + 2);
        compute_chunk(s);
        s++; if (s == NSTAGE) s = 0;
    }

    // epilogue: weighted deterministic scatter-add (2 contributions per element)
    #pragma unroll
    for (int mt = 0; mt < 4; mt++) {
        #pragma unroll
        for (int half = 0; half < 2; half++) {
            int rl = warpM * 64 + mt * 16 + half * 8 + g;
            int t = toks[rl];
            if (t >= 0) {
                float w = wgts[rl];
                float* orow = out + (size_t)t * DM + n0;
                #pragma unroll
                for (int nt = 0; nt < 8; nt++) {
                    int col = warpN * 64 + nt * 8 + 2 * tq;
                    atomicAdd(orow + col,     w * acc[mt][nt][half * 2 + 0]);
                    atomicAdd(orow + col + 1, w * acc[mt][nt][half * 2 + 1]);
                }
            }
        }
    }
}

// ---------------- launch ----------------
extern "C" void kernel_launch(void* const* d_in, const int* in_sizes, int n_in,
                              void* d_out, int out_size) {
    const float* x  = (const float*)d_in[0];   // [T, DM]
    const float* gw = (const float*)d_in[1];   // [NE, DM]
    const float* w1 = (const float*)d_in[2];   // [NE, FF, DM]
    const float* w3 = (const float*)d_in[3];   // [NE, FF, DM]
    const float* w2 = (const float*)d_in[4];   // [NE, DM, FF]

    float* out    = (float*)d_out;             // [T, DM] then router_logits [T, NE]
    float* logits = out + (size_t)T * DM;

    cudaFuncSetAttribute(gemm1_tc, cudaFuncAttributeMaxDynamicSharedMemorySize, G1_SMEM_BYTES);
    cudaFuncSetAttribute(gemm2_tc, cudaFuncAttributeMaxDynamicSharedMemorySize, G2_SMEM_BYTES);

    cudaMemsetAsync(d_out, 0, (size_t)T * DM * sizeof(float));
    init_kernel<<<1, 32>>>();
    router_kernel<<<T, 256>>>(x, gw, logits);
    assign_kernel<<<1, 256>>>();
    gemm1_tc<<<dim3(FF / 128, (2 * T) / 128, NE), 256, G1_SMEM_BYTES>>>(x, w1, w3);
    gemm2_tc<<<dim3(DM / 256, (2 * T) / 128, NE), 256, G2_SMEM_BYTES>>>(w2, out);
}

// round 11
// speedup vs baseline: 1.2987x; 1.2987x over previous
#include <cuda_runtime.h>
#include <cstdint>
#include <math.h>

// Problem constants (fixed shapes)
#define T    2048
#define DM   1024
#define NE   8
#define FF   4096

#define KC   32            // K floats per pipeline chunk
#define PAD  36            // smem row stride in floats (32 + 4)
#define NSTAGE 3

// ---------------- scratch (static device globals; no allocation) ----------------
__device__ int   g_count[NE];
__device__ int   g_cursor[NE];
__device__ int   g_offset[NE];
__device__ int   g_topk_idx[T * 2];
__device__ float g_topk_w[T * 2];
__device__ int   g_tok[2 * T];
__device__ float g_wgt[2 * T];
__device__ float g_inter[(size_t)(2 * T) * FF];   // 64 MB fp32 scratch (tf32-rounded values)

#define DEVINL __device__ __forceinline__

DEVINL uint32_t smem_u32(const void* p) {
    uint32_t a;
    asm("{ .reg .u64 t; cvta.to.shared.u64 t, %1; cvt.u32.u64 %0, t; }" : "=r"(a) : "l"(p));
    return a;
}

DEVINL uint32_t to_tf32(float f) {
    uint32_t r;
    asm("cvt.rna.tf32.f32 %0, %1;" : "=r"(r) : "f"(f));
    return r;
}
DEVINL float tf32f(float f) { return __uint_as_float(to_tf32(f)); }

DEVINL void cvt4(uint32_t* r) {
    r[0] = to_tf32(__uint_as_float(r[0]));
    r[1] = to_tf32(__uint_as_float(r[1]));
    r[2] = to_tf32(__uint_as_float(r[2]));
    r[3] = to_tf32(__uint_as_float(r[3]));
}

DEVINL void mma_tf32(float* d, const uint32_t* a, const uint32_t* b) {
    asm volatile(
        "mma.sync.aligned.m16n8k8.row.col.f32.tf32.tf32.f32 "
        "{%0,%1,%2,%3}, {%4,%5,%6,%7}, {%8,%9}, {%0,%1,%2,%3};"
        : "+f"(d[0]), "+f"(d[1]), "+f"(d[2]), "+f"(d[3])
        : "r"(a[0]), "r"(a[1]), "r"(a[2]), "r"(a[3]), "r"(b[0]), "r"(b[1]));
}

DEVINL void ldsm_x4(uint32_t addr, uint32_t* r) {
    asm volatile("ldmatrix.sync.aligned.m8n8.x4.shared.b16 {%0,%1,%2,%3}, [%4];"
        : "=r"(r[0]), "=r"(r[1]), "=r"(r[2]), "=r"(r[3]) : "r"(addr));
}

// cp.async 16B; src-size 0 zero-fills the destination
DEVINL void cp16(uint32_t dst, const void* src, bool valid) {
    asm volatile("cp.async.cg.shared.global [%0], [%1], 16, %2;"
        :: "r"(dst), "l"(src), "r"(valid ? 16u : 0u) : "memory");
}
DEVINL void cp16f(uint32_t dst, const void* src) {
    asm volatile("cp.async.cg.shared.global [%0], [%1], 16;"
        :: "r"(dst), "l"(src) : "memory");
}
#define CP_COMMIT() asm volatile("cp.async.commit_group;" ::: "memory")
#define CP_WAIT1()  asm volatile("cp.async.wait_group 1;" ::: "memory")
#define CP_WAIT0()  asm volatile("cp.async.wait_group 0;" ::: "memory")

// ---------------- init ----------------
__global__ void init_kernel() {
    int i = threadIdx.x;
    if (i < NE) { g_count[i] = 0; g_cursor[i] = 0; }
}

// ---------------- router ----------------
__global__ void router_kernel(const float* __restrict__ x,
                              const float* __restrict__ gw,
                              float* __restrict__ logits_out) {
    int t = blockIdx.x;
    int warp = threadIdx.x >> 5;
    int lane = threadIdx.x & 31;
    const float* xr = x + (size_t)t * DM;
    const float* gr = gw + (size_t)warp * DM;
    float s = 0.f;
    for (int j = lane; j < DM; j += 32) s += xr[j] * gr[j];
    #pragma unroll
    for (int o = 16; o > 0; o >>= 1) s += __shfl_xor_sync(0xFFFFFFFFu, s, o);

    __shared__ float lg[NE];
    if (lane == 0) lg[warp] = s;
    __syncthreads();

    if (threadIdx.x == 0) {
        float mx = lg[0];
        #pragma unroll
        for (int e = 1; e < NE; e++) mx = fmaxf(mx, lg[e]);
        float p[NE];
        #pragma unroll
        for (int e = 0; e < NE; e++) p[e] = expf(lg[e] - mx);
        int i0 = 0;
        #pragma unroll
        for (int e = 1; e < NE; e++) if (p[e] > p[i0]) i0 = e;
        int i1 = -1;
        #pragma unroll
        for (int e = 0; e < NE; e++) {
            if (e == i0) continue;
            if (i1 < 0 || p[e] > p[i1]) i1 = e;
        }
        float inv = 1.f / (p[i0] + p[i1]);
        g_topk_idx[t * 2 + 0] = i0;
        g_topk_idx[t * 2 + 1] = i1;
        g_topk_w[t * 2 + 0] = p[i0] * inv;
        g_topk_w[t * 2 + 1] = p[i1] * inv;
        atomicAdd(&g_count[i0], 1);
        atomicAdd(&g_count[i1], 1);
        #pragma unroll
        for (int e = 0; e < NE; e++) logits_out[(size_t)t * NE + e] = lg[e];
    }
}

// ---------------- offsets + assignment (single block) ----------------
__global__ void assign_kernel() {
    if (threadIdx.x == 0) {
        int o = 0;
        #pragma unroll
        for (int e = 0; e < NE; e++) { g_offset[e] = o; o += g_count[e]; }
    }
    __syncthreads();
    for (int t = threadIdx.x; t < T; t += blockDim.x) {
        #pragma unroll
        for (int k = 0; k < 2; k++) {
            int e = g_topk_idx[t * 2 + k];
            int pos = atomicAdd(&g_cursor[e], 1);
            int g = g_offset[e] + pos;
            g_tok[g] = t;
            g_wgt[g] = g_topk_w[t * 2 + k];
        }
    }
}

// smem sizing (uint32 units)
#define TILE128_U32 (128 * PAD)                      // 4608
#define TILE256_U32 (256 * PAD)                      // 9216
#define G1_SMEM_U32 (128 + NSTAGE * 3 * TILE128_U32)                 // 41600 u32
#define G2_SMEM_U32 (512 + NSTAGE * (TILE256_U32 + TILE128_U32))     // 41984 u32 (header = toks256+wgts256)
#define G1_SMEM_BYTES (G1_SMEM_U32 * 4)
#define G2_SMEM_BYTES (G2_SMEM_U32 * 4)

// ================= GEMM1: inter = silu(X w1^T) * (X w3^T) =================
// 512 threads, 16 warps (4M x 4N), block 128x128, warp tile 32x32 (mt=2, nt=4).
// cp.async 3-stage pipeline; cvt.rna after ldmatrix.
__global__ __launch_bounds__(512, 1)
void gemm1_tc(const float* __restrict__ x,
              const float* __restrict__ w1,
              const float* __restrict__ w3) {
    int e = blockIdx.z;
    int cnt = g_count[e];
    int m0 = blockIdx.y * 128;
    if (m0 >= cnt) return;
    int n0 = blockIdx.x * 128;
    int base = g_offset[e];

    extern __shared__ uint32_t sm[];
    int* toks = (int*)sm;
    uint32_t* Abuf  = sm + 128;                        // NSTAGE x TILE128
    uint32_t* B1buf = Abuf  + NSTAGE * TILE128_U32;
    uint32_t* B3buf = B1buf + NSTAGE * TILE128_U32;

    uint32_t sbA  = smem_u32(Abuf);
    uint32_t sbB1 = smem_u32(B1buf);
    uint32_t sbB3 = smem_u32(B3buf);

    int tid = threadIdx.x;
    int wid = tid >> 5, lane = tid & 31;
    int g = lane >> 2, tq = lane & 3;
    int grp = lane >> 3, rowi = lane & 7;
    int warpM = wid >> 2, warpN = wid & 3;     // 4(M) x 4(N)

    if (tid < 128) {
        int m = m0 + tid;
        toks[tid] = (m < cnt) ? g_tok[base + m] : -1;
    }
    __syncthreads();

    const float* W1 = w1 + (size_t)e * FF * DM + (size_t)n0 * DM;
    const float* W3 = w3 + (size_t)e * FF * DM + (size_t)n0 * DM;

    float acc1[2][4][4], acc3[2][4][4];
    #pragma unroll
    for (int i = 0; i < 2; i++)
        #pragma unroll
        for (int j = 0; j < 4; j++)
            #pragma unroll
            for (int c = 0; c < 4; c++) { acc1[i][j][c] = 0.f; acc3[i][j][c] = 0.f; }

    // producer: per tile 1024 f4 / 512 thr = 2 each, rows r0 and r0+64
    int pr0 = tid >> 3;                 // 0..63
    int pj  = tid & 7;                  // f4 column
    int tok0 = toks[pr0], tok1 = toks[pr0 + 64];
    const float* aSrc0 = x + (size_t)(tok0 >= 0 ? tok0 : 0) * DM;
    const float* aSrc1 = x + (size_t)(tok1 >= 0 ? tok1 : 0) * DM;
    const float* b1Src0 = W1 + (size_t)pr0 * DM;
    const float* b1Src1 = W1 + (size_t)(pr0 + 64) * DM;
    const float* b3Src0 = W3 + (size_t)pr0 * DM;
    const float* b3Src1 = W3 + (size_t)(pr0 + 64) * DM;
    uint32_t d0 = (uint32_t)(pr0 * PAD + pj * 4) * 4;
    uint32_t d1 = (uint32_t)((pr0 + 64) * PAD + pj * 4) * 4;
    int kj = pj * 4;

    auto load_chunk = [&](int it) {
        int s = it - (it / NSTAGE) * NSTAGE;
        int k0 = it * KC;
        uint32_t sOff = (uint32_t)(s * TILE128_U32) * 4;
        cp16(sbA + sOff + d0, aSrc0 + k0 + kj, tok0 >= 0);
        cp16(sbA + sOff + d1, aSrc1 + k0 + kj, tok1 >= 0);
        cp16f(sbB1 + sOff + d0, b1Src0 + k0 + kj);
        cp16f(sbB1 + sOff + d1, b1Src1 + k0 + kj);
        cp16f(sbB3 + sOff + d0, b3Src0 + k0 + kj);
        cp16f(sbB3 + sOff + d1, b3Src1 + k0 + kj);
        CP_COMMIT();
    };

    // hoisted fragment byte offsets (within a tile)
    uint32_t aOff = (uint32_t)((warpM * 32 + (grp & 1) * 8 + rowi) * PAD + (grp >> 1) * 4) * 4;
    uint32_t bOff = (uint32_t)((warpN * 32 + (grp >> 1) * 8 + rowi) * PAD + (grp & 1) * 4) * 4;

    auto compute_chunk = [&](int s) {
        uint32_t sOff = (uint32_t)(s * TILE128_U32) * 4;
        uint32_t Ab  = sbA  + sOff + aOff;
        uint32_t B1b = sbB1 + sOff + bOff;
        uint32_t B3b = sbB3 + sOff + bOff;
        #pragma unroll
        for (int ks = 0; ks < 4; ks++) {
            uint32_t kb = (uint32_t)(ks * 32);
            uint32_t afr[2][4];
            #pragma unroll
            for (int mt = 0; mt < 2; mt++) {
                ldsm_x4(Ab + kb + (uint32_t)(mt * 16 * PAD * 4), afr[mt]);
                cvt4(afr[mt]);
            }
            uint32_t b1f[2][4], b3f[2][4];
            #pragma unroll
            for (int np = 0; np < 2; np++) {
                uint32_t off = kb + (uint32_t)(np * 16 * PAD * 4);
                ldsm_x4(B1b + off, b1f[np]);
                ldsm_x4(B3b + off, b3f[np]);
                cvt4(b1f[np]);
                cvt4(b3f[np]);
            }
            #pragma unroll
            for (int np = 0; np < 2; np++) {
                #pragma unroll
                for (int sub = 0; sub < 2; sub++) {
                    int nt = np * 2 + sub;
                    #pragma unroll
                    for (int mt = 0; mt < 2; mt++) {
                        mma_tf32(acc1[mt][nt], afr[mt], &b1f[np][sub * 2]);
                        mma_tf32(acc3[mt][nt], afr[mt], &b3f[np][sub * 2]);
                    }
                }
            }
        }
    };

    const int NIT = DM / KC;   // 32
    load_chunk(0);
    load_chunk(1);
    int s = 0;
    for (int it = 0; it < NIT; ++it) {
        if (it == NIT - 1) { CP_WAIT0(); } else { CP_WAIT1(); }
        __syncthreads();
        if (it + 2 < NIT) load_chunk(it + 2);
        compute_chunk(s);
        s++; if (s == NSTAGE) s = 0;
    }

    // epilogue: silu(up) * gate, tf32-rounded -> g_inter (valid rows only)
    #pragma unroll
    for (int mt = 0; mt < 2; mt++) {
        #pragma unroll
        for (int half = 0; half < 2; half++) {
            int rl = warpM * 32 + mt * 16 + half * 8 + g;
            int m = m0 + rl;
            if (m < cnt) {
                float* orow = g_inter + (size_t)(base + m) * FF + n0;
                #pragma unroll
                for (int nt = 0; nt < 4; nt++) {
                    int col = warpN * 32 + nt * 8 + 2 * tq;
                    float u0 = acc1[mt][nt][half * 2 + 0];
                    float u1 = acc1[mt][nt][half * 2 + 1];
                    float g0 = acc3[mt][nt][half * 2 + 0];
                    float g1 = acc3[mt][nt][half * 2 + 1];
                    float2 o;
                    o.x = tf32f(u0 / (1.f + __expf(-u0)) * g0);
                    o.y = tf32f(u1 / (1.f + __expf(-u1)) * g1);
                    *(float2*)(orow + col) = o;
                }
            }
        }
    }
}

// ================= GEMM2: out += cw * (inter w2^T) =================
// 512 threads, 16 warps (4M x 4N), block 256x128, warp tile 64x32 (mt=4, nt=4).
// A (g_inter) pre-rounded tf32 -> no cvt; B (w2) cvt after ldmatrix.
__global__ __launch_bounds__(512, 1)
void gemm2_tc(const float* __restrict__ w2, float* __restrict__ out) {
    int e = blockIdx.z;
    int cnt = g_count[e];
    int m0 = blockIdx.y * 256;
    if (m0 >= cnt) return;
    int n0 = blockIdx.x * 128;
    int base = g_offset[e];

    extern __shared__ uint32_t sm[];
    int*   toks = (int*)sm;                     // [256]
    float* wgts = (float*)(sm + 256);           // [256]
    uint32_t* Abuf = sm + 512;                  // NSTAGE x TILE256
    uint32_t* Bbuf = Abuf + NSTAGE * TILE256_U32;   // NSTAGE x TILE128

    uint32_t sbA = smem_u32(Abuf);
    uint32_t sbB = smem_u32(Bbuf);

    int tid = threadIdx.x;
    int wid = tid >> 5, lane = tid & 31;
    int g = lane >> 2, tq = lane & 3;
    int grp = lane >> 3, rowi = lane & 7;
    int warpM = wid >> 2, warpN = wid & 3;   // 4(M) x 4(N)

    if (tid < 256) {
        int m = m0 + tid;
        bool v = (m < cnt);
        toks[tid] = v ? g_tok[base + m] : -1;
        wgts[tid] = v ? g_wgt[base + m] : 0.f;
    }
    __syncthreads();

    const float* W2 = w2 + (size_t)e * DM * FF + (size_t)n0 * FF;
    const float* Ain = g_inter + (size_t)(base + m0) * FF;
    int mlim = cnt - m0;

    float acc[4][4][4];
    #pragma unroll
    for (int i = 0; i < 4; i++)
        #pragma unroll
        for (int j = 0; j < 4; j++)
            #pragma unroll
            for (int c = 0; c < 4; c++) acc[i][j][c] = 0.f;

    // producer: A 256 rows x 8 f4 (4 per thread: rows r0+{0,64,128,192});
    //           B 128 rows x 8 f4 (2 per thread: rows r0+{0,64})
    int pr0 = tid >> 3;
    int pj  = tid & 7;
    int kj  = pj * 4;
    bool av[4];
    const float* aS[4];
    uint32_t ad[4];
    #pragma unroll
    for (int p = 0; p < 4; p++) {
        int row = pr0 + p * 64;
        av[p] = (row < mlim);
        aS[p] = Ain + (size_t)(av[p] ? row : 0) * FF;
        ad[p] = (uint32_t)(row * PAD + pj * 4) * 4;
    }
    const float* bS0 = W2 + (size_t)pr0 * FF;
    const float* bS1 = W2 + (size_t)(pr0 + 64) * FF;
    uint32_t bd0 = (uint32_t)(pr0 * PAD + pj * 4) * 4;
    uint32_t bd1 = (uint32_t)((pr0 + 64) * PAD + pj * 4) * 4;

    auto load_chunk = [&](int it) {
        int s = it - (it / NSTAGE) * NSTAGE;
        int k0 = it * KC;
        uint32_t Aoff = (uint32_t)(s * TILE256_U32) * 4;
        uint32_t Boff = (uint32_t)(s * TILE128_U32) * 4;
        #pragma unroll
        for (int p = 0; p < 4; p++)
            cp16(sbA + Aoff + ad[p], aS[p] + k0 + kj, av[p]);
        cp16f(sbB + Boff + bd0, bS0 + k0 + kj);
        cp16f(sbB + Boff + bd1, bS1 + k0 + kj);
        CP_COMMIT();
    };

    uint32_t aOff = (uint32_t)((warpM * 64 + (grp & 1) * 8 + rowi) * PAD + (grp >> 1) * 4) * 4;
    uint32_t bOff = (uint32_t)((warpN * 32 + (grp >> 1) * 8 + rowi) * PAD + (grp & 1) * 4) * 4;

    auto compute_chunk = [&](int s) {
        uint32_t Ab = sbA + (uint32_t)(s * TILE256_U32) * 4 + aOff;
        uint32_t Bb = sbB + (uint32_t)(s * TILE128_U32) * 4 + bOff;
        #pragma unroll
        for (int ks = 0; ks < 4; ks++) {
            uint32_t kb = (uint32_t)(ks * 32);
            uint32_t afr[4][4];
            #pragma unroll
            for (int mt = 0; mt < 4; mt++)
                ldsm_x4(Ab + kb + (uint32_t)(mt * 16 * PAD * 4), afr[mt]);  // pre-rounded tf32
            uint32_t bf[2][4];
            #pragma unroll
            for (int np = 0; np < 2; np++) {
                ldsm_x4(Bb + kb + (uint32_t)(np * 16 * PAD * 4), bf[np]);
                cvt4(bf[np]);
            }
            #pragma unroll
            for (int np = 0; np < 2; np++) {
                #pragma unroll
                for (int sub = 0; sub < 2; sub++) {
                    int nt = np * 2 + sub;
                    #pragma unroll
                    for (int mt = 0; mt < 4; mt++)
                        mma_tf32(acc[mt][nt], afr[mt], &bf[np][sub * 2]);
                }
            }
        }
    };

    const int NIT = FF / KC;   // 128
    load_chunk(0);
    load_chunk(1);
    int s = 0;
    for (int it = 0; it < NIT; ++it) {
        if (it == NIT - 1) { CP_WAIT0(); } else { CP_WAIT1(); }
        __syncthreads();
        if (it + 2 < NIT) load_chunk(it + 2);
        compute_chunk(s);
        s++; if (s == NSTAGE) s = 0;
    }

    // epilogue: weighted deterministic scatter-add (2 contributions per element)
    #pragma unroll
    for (int mt = 0; mt < 4; mt++) {
        #pragma unroll
        for (int half = 0; half < 2; half++) {
            int rl = warpM * 64 + mt * 16 + half * 8 + g;
            int t = toks[rl];
            if (t >= 0) {
                float w = wgts[rl];
                float* orow = out + (size_t)t * DM + n0;
                #pragma unroll
                for (int nt = 0; nt < 4; nt++) {
                    int col = warpN * 32 + nt * 8 + 2 * tq;
                    atomicAdd(orow + col,     w * acc[mt][nt][half * 2 + 0]);
                    atomicAdd(orow + col + 1, w * acc[mt][nt][half * 2 + 1]);
                }
            }
        }
    }
}

// ---------------- launch ----------------
extern "C" void kernel_launch(void* const* d_in, const int* in_sizes, int n_in,
                              void* d_out, int out_size) {
    const float* x  = (const float*)d_in[0];   // [T, DM]
    const float* gw = (const float*)d_in[1];   // [NE, DM]
    const float* w1 = (const float*)d_in[2];   // [NE, FF, DM]
    const float* w3 = (const float*)d_in[3];   // [NE, FF, DM]
    const float* w2 = (const float*)d_in[4];   // [NE, DM, FF]

    float* out    = (float*)d_out;             // [T, DM] then router_logits [T, NE]
    float* logits = out + (size_t)T * DM;

    cudaFuncSetAttribute(gemm1_tc, cudaFuncAttributeMaxDynamicSharedMemorySize, G1_SMEM_BYTES);
    cudaFuncSetAttribute(gemm2_tc, cudaFuncAttributeMaxDynamicSharedMemorySize, G2_SMEM_BYTES);

    cudaMemsetAsync(d_out, 0, (size_t)T * DM * sizeof(float));
    init_kernel<<<1, 32>>>();
    router_kernel<<<T, 256>>>(x, gw, logits);
    assign_kernel<<<1, 256>>>();
    gemm1_tc<<<dim3(FF / 128, (2 * T) / 128, NE), 512, G1_SMEM_BYTES>>>(x, w1, w3);
    gemm2_tc<<<dim3(DM / 128, (2 * T) / 256, NE), 512, G2_SMEM_BYTES>>>(w2, out);
}